// round 11
// baseline (speedup 1.0000x reference)
#include <cuda_runtime.h>
#include <cuda_bf16.h>
#include <cstring>

#define OBS   20
#define PRED  30
#define B_AG  32768
#define ROW2  65536
#define HD    64
#define ED    16
#define KD    80
#define NG    256
#define AB    256               // agents per block
#define NTHR  512
#define NBLK  (B_AG / AB)       // 128 blocks -> all co-resident (148 SMs)
#define KSTR  88                // bf16 row stride (44 words: 16B-aligned + conflict-free)
#define RB    176               // row bytes

// ---- smem byte layout ----
#define SM_WHI   0               // 256*176 = 45056
#define SM_WLO   45056
#define SM_AHI   90112
#define SM_ALO   135168
#define SM_SMALL 180224          // 1280 floats
#define SM_STAGE 185344          // 256*41 floats = 41984 B (phase-1 staging)
#define SM_TOTAL 227328
// smalls float offsets
#define O_EMBW 0
#define O_EMBB 640
#define O_LN1G 656
#define O_LN1B 696
#define O_GW   736    // float2[64]: (ln2g*w0, ln2g*w1) per j
#define O_SC   864    // SGW0, SGW1, CB0, CB1
#define O_BIAS 1024   // 256 floats, gate-interleaved (n' = 4j+gate)

// persistent state + prepped params. c stored [j][agent].
__device__ __align__(16) float          g_c[HD * B_AG];
__device__ __align__(16) unsigned short g_Whi[NG * KSTR];
__device__ __align__(16) unsigned short g_Wlo[NG * KSTR];
__device__ __align__(16) float          g_smalls[1280];
__device__ unsigned g_bar;     // grid barrier counter (reset by prep each replay)

// ---- helpers ----
__device__ __forceinline__ void cp16(unsigned s, const void* g) {
    asm volatile("cp.async.cg.shared.global [%0], [%1], 16;" :: "r"(s), "l"(g));
}
__device__ __forceinline__ unsigned pkbf(float a, float b) {
    __nv_bfloat162 t = __floats2bfloat162_rn(a, b);
    unsigned u; memcpy(&u, &t, 4); return u;
}
__device__ __forceinline__ void split(float v, float& hi, float& lo) {
    __nv_bfloat16 h = __float2bfloat16(v);
    hi = __bfloat162float(h);
    lo = v - hi;
}
__device__ __forceinline__ float tanhA(float x) {
    float r; asm("tanh.approx.f32 %0, %1;" : "=f"(r) : "f"(x)); return r;
}
__device__ __forceinline__ float sigmA(float x) {
    return fmaf(tanhA(0.5f * x), 0.5f, 0.5f);
}
__device__ __forceinline__ void ldsm4(unsigned& r0, unsigned& r1, unsigned& r2, unsigned& r3,
                                      unsigned addr) {
    asm volatile("ldmatrix.sync.aligned.m8n8.x4.shared.b16 {%0,%1,%2,%3}, [%4];"
                 : "=r"(r0), "=r"(r1), "=r"(r2), "=r"(r3) : "r"(addr));
}
__device__ __forceinline__ void ldsm2(unsigned& r0, unsigned& r1, unsigned addr) {
    asm volatile("ldmatrix.sync.aligned.m8n8.x2.shared.b16 {%0,%1}, [%2];"
                 : "=r"(r0), "=r"(r1) : "r"(addr));
}
__device__ __forceinline__ void mma16816(float& d0, float& d1, float& d2, float& d3,
                                         unsigned a0, unsigned a1, unsigned a2, unsigned a3,
                                         unsigned b0, unsigned b1) {
    asm volatile(
        "mma.sync.aligned.m16n8k16.row.col.f32.bf16.bf16.f32 "
        "{%0,%1,%2,%3}, {%4,%5,%6,%7}, {%8,%9}, {%0,%1,%2,%3};"
        : "+f"(d0), "+f"(d1), "+f"(d2), "+f"(d3)
        : "r"(a0), "r"(a1), "r"(a2), "r"(a3), "r"(b0), "r"(b1));
}
__device__ __forceinline__ unsigned ldvol(unsigned* p) {
    unsigned v;
    asm volatile("ld.volatile.global.u32 %0, [%1];" : "=r"(v) : "l"(p));
    return v;
}

// ---------------- one-time prep ----------------
__global__ void prep_kernel(const float* __restrict__ W_ih, const float* __restrict__ W_hh,
                            const float* __restrict__ b_ih, const float* __restrict__ b_hh,
                            const float* __restrict__ embW, const float* __restrict__ embB,
                            const float* __restrict__ ln1g, const float* __restrict__ ln1b,
                            const float* __restrict__ ln2g, const float* __restrict__ ln2b,
                            const float* __restrict__ h2pW, const float* __restrict__ h2pB)
{
    const int gid = blockIdx.x * blockDim.x + threadIdx.x;
    if (gid == 0) g_bar = 0;
    if (gid < NG * KD) {
        const int np = gid / KD;
        const int k  = gid % KD;
        const int n  = (np & 3) * HD + (np >> 2);   // gate-interleaved rows
        float w = (k < ED) ? W_ih[n * ED + k] : W_hh[n * HD + (k - ED)];
        float hi, lo; split(w, hi, lo);
        __nv_bfloat16 hb = __float2bfloat16(hi);
        __nv_bfloat16 lb = __float2bfloat16(lo);
        unsigned short hs, ls; memcpy(&hs, &hb, 2); memcpy(&ls, &lb, 2);
        g_Whi[np * KSTR + k] = hs;
        g_Wlo[np * KSTR + k] = ls;
    }
    if (gid < 1280) {
        float v;
        if (gid < 640)       v = embW[gid];
        else if (gid < 656)  v = embB[gid - 640];
        else if (gid < 696)  v = ln1g[gid - 656];
        else if (gid < 736)  v = ln1b[gid - 696];
        else if (gid < 864) {                       // gw pairs
            int q = gid - 736;
            int j = q >> 1;
            v = ln2g[j] * h2pW[(q & 1) * 64 + j];
        }
        else if (gid < 868) {                       // scalars
            int w = gid - 864;
            float acc = 0.f;
            if (w < 2) { for (int j = 0; j < 64; j++) acc += ln2g[j] * h2pW[w * 64 + j]; }
            else {
                int o = w - 2;
                for (int j = 0; j < 64; j++) acc += ln2b[j] * h2pW[o * 64 + j];
                acc += h2pB[o];
            }
            v = acc;
        }
        else if (gid >= 1024) {
            int np = gid - 1024;
            int n  = (np & 3) * HD + (np >> 2);
            v = b_ih[n] + b_hh[n];
        }
        else                 v = 0.f;
        g_smalls[gid] = v;
    }
    if (gid < B_AG * HD) g_c[gid] = 0.f;   // [j][agent], zero-init
}

// ---------------- persistent kernel: all 30 steps ----------------
__global__ void __launch_bounds__(NTHR, 1)
lstm_persist(const float* __restrict__ trajAbs,
             const float* __restrict__ decoderH,
             float* __restrict__ out)
{
    extern __shared__ char sm[];
    float* sSm    = (float*)(sm + SM_SMALL);
    float* sBias  = sSm + O_BIAS;
    float* sStage = (float*)(sm + SM_STAGE);

    const int tid  = threadIdx.x;
    const int lane = tid & 31;
    const int wid  = tid >> 5;
    const int b0   = blockIdx.x * AB;
    const unsigned sb = (unsigned)__cvta_generic_to_shared(sm);

    // ---- one-time: W tiles (90 KB), smalls, initial h -> A cols 16..79 ----
    {
#pragma unroll
        for (int i = 0; i < 6; i++) {
            int c = tid + i * NTHR;
            if (c < 2816) {
                cp16(sb + SM_WHI + c * 16, (const char*)g_Whi + c * 16);
                cp16(sb + SM_WLO + c * 16, (const char*)g_Wlo + c * 16);
            }
        }
        asm volatile("cp.async.commit_group;");
    }
    if (tid < 320) ((float4*)sSm)[tid] = ((const float4*)g_smalls)[tid];
    {
        // decoderH: (1, B, H) row-major -> agent-major float4 loads
#pragma unroll
        for (int it = 0; it < 8; it++) {
            int idx = tid + it * NTHR;       // 4096 float4s
            int a = idx >> 4;
            int j = (idx & 15) * 4;
            float4 hv = *(const float4*)(decoderH + (b0 + a) * HD + j);
            float h0,l0,h1,l1,h2,l2,h3,l3;
            split(hv.x,h0,l0); split(hv.y,h1,l1); split(hv.z,h2,l2); split(hv.w,h3,l3);
            unsigned off = a * RB + (16 + j) * 2;
            *(unsigned*)(sm + SM_AHI + off)     = pkbf(h0, h1);
            *(unsigned*)(sm + SM_AHI + off + 4) = pkbf(h2, h3);
            *(unsigned*)(sm + SM_ALO + off)     = pkbf(l0, l1);
            *(unsigned*)(sm + SM_ALO + off + 4) = pkbf(l2, l3);
        }
    }
    asm volatile("cp.async.wait_group 0;");
    __syncthreads();

    // invariant lane constants
    const int g    = lane >> 2;
    const int tig  = lane & 3;
    const int oddp = tig & 1;
    const int a_loc = wid * 16 + g + (oddp ? 8 : 0);
    const int bglob = b0 + a_loc;
    const unsigned abase = (wid * 16 + ((lane >> 3) & 1) * 8 + (lane & 7)) * RB
                         + (lane >> 4) * 16;
    const unsigned brow4_0 = (lane & 7) * RB + (lane >> 3) * 16;
    const unsigned brow2_0 = (lane & 7) * RB + 128 + ((lane >> 3) & 1) * 16;
    const int jj_base = tig >> 1;

    for (int s = 0; s < PRED; s++) {
        // ---------------- phase 1a: coalesced gather -> staging smem -------------
        // agent b's 40 features are flat elements [b*40, b*40+40) of the rolled
        // buffer concat(trajAbs[s*ROW2:], out[:...]) -> block window is contiguous.
        {
            const int base = s * ROW2 + b0 * 40;
#pragma unroll
            for (int i = 0; i < 20; i++) {
                int idx  = tid + i * NTHR;          // 0..10239
                int gidx = base + idx;
                float v = (gidx < OBS * ROW2) ? trajAbs[gidx]
                                              : out[gidx - OBS * ROW2];
                sStage[(idx / 40) * 41 + (idx % 40)] = v;
            }
        }
        __syncthreads();

        // ---------------- phase 1b: LN1 + embed + leaky -> A cols 0..15 ----------
        {
            const int a  = tid >> 1;
            const int jt = tid & 1;
            float raw[20];
            const float* sp = sStage + a * 41 + jt * 20;
#pragma unroll
            for (int u = 0; u < 20; u++) raw[u] = sp[u];

            float sum = 0.f, sq = 0.f;
#pragma unroll
            for (int u = 0; u < 20; u++) { sum += raw[u]; sq += raw[u] * raw[u]; }
            sum += __shfl_xor_sync(0xffffffffu, sum, 1);
            sq  += __shfl_xor_sync(0xffffffffu, sq, 1);
            const float mean = sum * 0.025f;
            const float var  = sq * 0.025f - mean * mean;
            const float rstd = rsqrtf(var + 1e-5f);

            float p[16];
#pragma unroll
            for (int e = 0; e < 16; e++) p[e] = 0.f;
#pragma unroll
            for (int u = 0; u < 20; u++) {
                int idx = jt * 20 + u;
                float xn = (raw[u] - mean) * rstd * sSm[O_LN1G + idx] + sSm[O_LN1B + idx];
#pragma unroll
                for (int e = 0; e < 16; e++) p[e] += xn * sSm[O_EMBW + e * 40 + idx];
            }
#pragma unroll
            for (int e = 0; e < 16; e++)
                p[e] += __shfl_xor_sync(0xffffffffu, p[e], 1);

#pragma unroll
            for (int i = 0; i < 4; i++) {
                int e = jt * 8 + 2 * i;
                float v0 = p[e]   + sSm[O_EMBB + e];
                float v1 = p[e+1] + sSm[O_EMBB + e + 1];
                v0 = v0 > 0.f ? v0 : 0.01f * v0;
                v1 = v1 > 0.f ? v1 : 0.01f * v1;
                float h0, l0, h1, l1;
                split(v0, h0, l0); split(v1, h1, l1);
                unsigned off = a * RB + e * 2;
                *(unsigned*)(sm + SM_AHI + off) = pkbf(h0, h1);
                *(unsigned*)(sm + SM_ALO + off) = pkbf(l0, l1);
            }
        }
        __syncthreads();

        // ---------------- A-fragment preload via ldmatrix -----------------------
        unsigned ahi[5][4], alo[5][4];
#pragma unroll
        for (int kt = 0; kt < 5; kt++) {
            ldsm4(ahi[kt][0], ahi[kt][1], ahi[kt][2], ahi[kt][3],
                  sb + SM_AHI + abase + kt * 32);
            ldsm4(alo[kt][0], alo[kt][1], alo[kt][2], alo[kt][3],
                  sb + SM_ALO + abase + kt * 32);
        }
        __syncthreads();

        // ---------------- GEMM + fused LSTM cell + fused LN2/h2p ----------------
        unsigned brow4 = brow4_0, brow2 = brow2_0;
        float sum_h = 0.f, sq_h = 0.f, S0 = 0.f, S1 = 0.f;

#pragma unroll 1
        for (int nt = 0; nt < 32; nt++) {
            const int jj   = 2 * nt + jj_base;
            const int cidx = jj * B_AG + bglob;
            float c_old = g_c[cidx];

            unsigned bh[10], bl[10];
            ldsm4(bh[0], bh[1], bh[2], bh[3], sb + SM_WHI + brow4);
            ldsm4(bh[4], bh[5], bh[6], bh[7], sb + SM_WHI + brow4 + 64);
            ldsm2(bh[8], bh[9],              sb + SM_WHI + brow2);
            ldsm4(bl[0], bl[1], bl[2], bl[3], sb + SM_WLO + brow4);
            ldsm4(bl[4], bl[5], bl[6], bl[7], sb + SM_WLO + brow4 + 64);
            ldsm2(bl[8], bl[9],              sb + SM_WLO + brow2);
            brow4 += 8 * RB; brow2 += 8 * RB;

            float d0 = 0.f, d1 = 0.f, d2 = 0.f, d3 = 0.f;
#pragma unroll
            for (int kt = 0; kt < 5; kt++) {
                mma16816(d0, d1, d2, d3, ahi[kt][0], ahi[kt][1], ahi[kt][2], ahi[kt][3],
                         bh[2*kt], bh[2*kt+1]);
                mma16816(d0, d1, d2, d3, ahi[kt][0], ahi[kt][1], ahi[kt][2], ahi[kt][3],
                         bl[2*kt], bl[2*kt+1]);
                mma16816(d0, d1, d2, d3, alo[kt][0], alo[kt][1], alo[kt][2], alo[kt][3],
                         bh[2*kt], bh[2*kt+1]);
            }
            // lane exchange: one full (i,f,g,o) cell per lane
            float r0 = __shfl_xor_sync(0xffffffffu, d0, 1);
            float r1 = __shfl_xor_sync(0xffffffffu, d1, 1);
            float r2 = __shfl_xor_sync(0xffffffffu, d2, 1);
            float r3 = __shfl_xor_sync(0xffffffffu, d3, 1);
            float iv = oddp ? r2 : d0;
            float fv = oddp ? r3 : d1;
            float gv = oddp ? d2 : r0;
            float ov = oddp ? d3 : r1;
            float4 bias = *(const float4*)(sBias + 4 * jj);
            iv += bias.x; fv += bias.y; gv += bias.z; ov += bias.w;

            float ig = sigmA(iv);
            float fg = sigmA(fv);
            float og = sigmA(ov);
            float gg = tanhA(gv);
            float c2 = fmaf(fg, c_old, ig * gg);
            float hv = og * tanhA(c2);
            g_c[cidx] = c2;

            // write h split directly into A tile (cols 16..79) for next step
            float hh, hl;
            split(hv, hh, hl);
            unsigned hoff = a_loc * RB + (16 + jj) * 2;
            *(__nv_bfloat16*)(sm + SM_AHI + hoff) = __float2bfloat16(hh);
            *(__nv_bfloat16*)(sm + SM_ALO + hoff) = __float2bfloat16(hl);

            sum_h += hv;
            sq_h   = fmaf(hv, hv, sq_h);
            float2 gw = *(const float2*)(sSm + O_GW + 2 * jj);
            S0 = fmaf(hv, gw.x, S0);
            S1 = fmaf(hv, gw.y, S1);
        }

        // reduce across the 2 lanes sharing this agent (tig ^ 2)
        sum_h += __shfl_xor_sync(0xffffffffu, sum_h, 2);
        sq_h  += __shfl_xor_sync(0xffffffffu, sq_h, 2);
        S0    += __shfl_xor_sync(0xffffffffu, S0, 2);
        S1    += __shfl_xor_sync(0xffffffffu, S1, 2);

        if (tig < 2) {
            const float m    = sum_h * 0.015625f;
            const float var  = sq_h * 0.015625f - m * m;
            const float rstd = rsqrtf(var + 1e-5f);
            float2 r = make_float2(rstd * (S0 - m * sSm[O_SC + 0]) + sSm[O_SC + 2],
                                   rstd * (S1 - m * sSm[O_SC + 1]) + sSm[O_SC + 3]);
            *(float2*)(out + s * ROW2 + bglob * 2) = r;
        }

        // ---------------- grid barrier (skip after last step) --------------------
        if (s < PRED - 1) {
            __threadfence();
            __syncthreads();
            if (tid == 0) {
                atomicAdd(&g_bar, 1u);
                const unsigned target = (unsigned)(s + 1) * (unsigned)gridDim.x;
                while (ldvol(&g_bar) < target) __nanosleep(64);
            }
            __syncthreads();
            __threadfence();
        }
    }
}

extern "C" void kernel_launch(void* const* d_in, const int* in_sizes, int n_in,
                              void* d_out, int out_size)
{
    const float* trajAbs  = (const float*)d_in[0];
    const float* decoderH = (const float*)d_in[2];
    const float* W_ih = (const float*)d_in[3];
    const float* W_hh = (const float*)d_in[4];
    const float* b_ih = (const float*)d_in[5];
    const float* b_hh = (const float*)d_in[6];
    const float* embW = (const float*)d_in[7];
    const float* embB = (const float*)d_in[8];
    const float* h2pW = (const float*)d_in[9];
    const float* h2pB = (const float*)d_in[10];
    const float* ln1g = (const float*)d_in[11];
    const float* ln1b = (const float*)d_in[12];
    const float* ln2g = (const float*)d_in[13];
    const float* ln2b = (const float*)d_in[14];
    float* out = (float*)d_out;

    prep_kernel<<<(B_AG * HD + 255) / 256, 256>>>(
        W_ih, W_hh, b_ih, b_hh, embW, embB,
        ln1g, ln1b, ln2g, ln2b, h2pW, h2pB);

    cudaFuncSetAttribute(lstm_persist, cudaFuncAttributeMaxDynamicSharedMemorySize,
                         SM_TOTAL);

    lstm_persist<<<NBLK, NTHR, SM_TOTAL>>>(trajAbs, decoderH, out);
}

// round 12
// speedup vs baseline: 1.5321x; 1.5321x over previous
#include <cuda_runtime.h>
#include <cuda_fp16.h>
#include <cstring>

#define OBS   20
#define PRED  30
#define B_AG  32768
#define ROW2  65536
#define HD    64
#define ED    16
#define KD    80
#define NG    256
#define AB    256               // agents per block
#define NTHR  512
#define NBLK  (B_AG / AB)       // 128 blocks -> all co-resident (148 SMs)
#define KSTR  88                // fp16 row stride (44 words: 16B-aligned + conflict-free)
#define RB    176               // row bytes

// ---- smem byte layout ----
#define SM_W     0               // 256*176 = 45056 (fp16 W, gate-interleaved rows)
#define SM_A     45056           // 45056 (fp16 A tile: x cols 0..15, h cols 16..79)
#define SM_SMALL 90112           // 1280 floats = 5120
#define SM_C     95232           // 256*66*4 = 67584 (c state, [a][jj] stride 66)
#define SM_STAGE 162816          // 256*41*4 = 41984 (phase-1 staging)
#define SM_TOTAL 204800
// smalls float offsets
#define O_EMBW 0
#define O_EMBB 640
#define O_LN1G 656
#define O_LN1B 696
#define O_GW   736    // float2[64]: (ln2g*w0, ln2g*w1) per j
#define O_SC   864    // SGW0, SGW1, CB0, CB1
#define O_BIAS 1024   // 256 floats, gate-interleaved (n' = 4j+gate)

// prepped params (c now lives in smem; no global state round-trip)
__device__ __align__(16) unsigned short g_W[NG * KSTR];
__device__ __align__(16) float          g_smalls[1280];
__device__ unsigned g_bar;     // grid barrier counter (reset by prep each replay)

// ---- helpers ----
__device__ __forceinline__ void cp16(unsigned s, const void* g) {
    asm volatile("cp.async.cg.shared.global [%0], [%1], 16;" :: "r"(s), "l"(g));
}
__device__ __forceinline__ unsigned pkh2(float a, float b) {
    __half2 t = __floats2half2_rn(a, b);
    unsigned u; memcpy(&u, &t, 4); return u;
}
__device__ __forceinline__ float tanhA(float x) {
    float r; asm("tanh.approx.f32 %0, %1;" : "=f"(r) : "f"(x)); return r;
}
__device__ __forceinline__ float sigmA(float x) {
    return fmaf(tanhA(0.5f * x), 0.5f, 0.5f);
}
__device__ __forceinline__ void ldsm4(unsigned& r0, unsigned& r1, unsigned& r2, unsigned& r3,
                                      unsigned addr) {
    asm volatile("ldmatrix.sync.aligned.m8n8.x4.shared.b16 {%0,%1,%2,%3}, [%4];"
                 : "=r"(r0), "=r"(r1), "=r"(r2), "=r"(r3) : "r"(addr));
}
__device__ __forceinline__ void ldsm2(unsigned& r0, unsigned& r1, unsigned addr) {
    asm volatile("ldmatrix.sync.aligned.m8n8.x2.shared.b16 {%0,%1}, [%2];"
                 : "=r"(r0), "=r"(r1) : "r"(addr));
}
__device__ __forceinline__ void mma16816(float& d0, float& d1, float& d2, float& d3,
                                         unsigned a0, unsigned a1, unsigned a2, unsigned a3,
                                         unsigned b0, unsigned b1) {
    asm volatile(
        "mma.sync.aligned.m16n8k16.row.col.f32.f16.f16.f32 "
        "{%0,%1,%2,%3}, {%4,%5,%6,%7}, {%8,%9}, {%0,%1,%2,%3};"
        : "+f"(d0), "+f"(d1), "+f"(d2), "+f"(d3)
        : "r"(a0), "r"(a1), "r"(a2), "r"(a3), "r"(b0), "r"(b1));
}
__device__ __forceinline__ unsigned ldvol(unsigned* p) {
    unsigned v;
    asm volatile("ld.volatile.global.u32 %0, [%1];" : "=r"(v) : "l"(p));
    return v;
}

// ---------------- one-time prep ----------------
__global__ void prep_kernel(const float* __restrict__ W_ih, const float* __restrict__ W_hh,
                            const float* __restrict__ b_ih, const float* __restrict__ b_hh,
                            const float* __restrict__ embW, const float* __restrict__ embB,
                            const float* __restrict__ ln1g, const float* __restrict__ ln1b,
                            const float* __restrict__ ln2g, const float* __restrict__ ln2b,
                            const float* __restrict__ h2pW, const float* __restrict__ h2pB)
{
    const int gid = blockIdx.x * blockDim.x + threadIdx.x;
    if (gid == 0) g_bar = 0;
    if (gid < NG * KD) {
        const int np = gid / KD;
        const int k  = gid % KD;
        const int n  = (np & 3) * HD + (np >> 2);   // gate-interleaved rows
        float w = (k < ED) ? W_ih[n * ED + k] : W_hh[n * HD + (k - ED)];
        __half h = __float2half(w);
        unsigned short hs; memcpy(&hs, &h, 2);
        g_W[np * KSTR + k] = hs;
    }
    if (gid < 1280) {
        float v;
        if (gid < 640)       v = embW[gid];
        else if (gid < 656)  v = embB[gid - 640];
        else if (gid < 696)  v = ln1g[gid - 656];
        else if (gid < 736)  v = ln1b[gid - 696];
        else if (gid < 864) {                       // gw pairs
            int q = gid - 736;
            int j = q >> 1;
            v = ln2g[j] * h2pW[(q & 1) * 64 + j];
        }
        else if (gid < 868) {                       // scalars
            int w = gid - 864;
            float acc = 0.f;
            if (w < 2) { for (int j = 0; j < 64; j++) acc += ln2g[j] * h2pW[w * 64 + j]; }
            else {
                int o = w - 2;
                for (int j = 0; j < 64; j++) acc += ln2b[j] * h2pW[o * 64 + j];
                acc += h2pB[o];
            }
            v = acc;
        }
        else if (gid >= 1024) {
            int np = gid - 1024;
            int n  = (np & 3) * HD + (np >> 2);
            v = b_ih[n] + b_hh[n];
        }
        else                 v = 0.f;
        g_smalls[gid] = v;
    }
}

// ---------------- persistent kernel: all 30 steps ----------------
__global__ void __launch_bounds__(NTHR, 1)
lstm_persist(const float* __restrict__ trajAbs,
             const float* __restrict__ decoderH,
             float* __restrict__ out)
{
    extern __shared__ char sm[];
    float* sSm    = (float*)(sm + SM_SMALL);
    float* sBias  = sSm + O_BIAS;
    float* sC     = (float*)(sm + SM_C);
    float* sStage = (float*)(sm + SM_STAGE);

    const int tid  = threadIdx.x;
    const int lane = tid & 31;
    const int wid  = tid >> 5;
    const int b0   = blockIdx.x * AB;
    const unsigned sb = (unsigned)__cvta_generic_to_shared(sm);

    // ---- one-time: W tile (44 KB), smalls, zero c, initial h -> A cols 16..79 ----
    {
#pragma unroll
        for (int i = 0; i < 6; i++) {
            int c = tid + i * NTHR;
            if (c < 2816) cp16(sb + SM_W + c * 16, (const char*)g_W + c * 16);
        }
        asm volatile("cp.async.commit_group;");
    }
    if (tid < 320) ((float4*)sSm)[tid] = ((const float4*)g_smalls)[tid];
#pragma unroll
    for (int i = 0; i < 33; i++) sC[tid + i * NTHR] = 0.f;   // 16896 words
    {
        // decoderH: (1, B, H) row-major -> agent-major float4 loads, fp16 pack
#pragma unroll
        for (int it = 0; it < 8; it++) {
            int idx = tid + it * NTHR;       // 4096 float4s
            int a = idx >> 4;
            int j = (idx & 15) * 4;
            float4 hv = *(const float4*)(decoderH + (b0 + a) * HD + j);
            unsigned off = a * RB + (16 + j) * 2;
            *(unsigned*)(sm + SM_A + off)     = pkh2(hv.x, hv.y);
            *(unsigned*)(sm + SM_A + off + 4) = pkh2(hv.z, hv.w);
        }
    }
    asm volatile("cp.async.wait_group 0;");
    __syncthreads();

    // invariant lane constants
    const int g    = lane >> 2;
    const int tig  = lane & 3;
    const int oddp = tig & 1;
    const int a_loc = wid * 16 + g + (oddp ? 8 : 0);
    const int bglob = b0 + a_loc;
    const unsigned abase = (wid * 16 + ((lane >> 3) & 1) * 8 + (lane & 7)) * RB
                         + (lane >> 4) * 16;
    const unsigned brow4_0 = sb + SM_W + (lane & 7) * RB + (lane >> 3) * 16;
    const unsigned brow2_0 = sb + SM_W + (lane & 7) * RB + 128 + ((lane >> 3) & 1) * 16;
    const int jj_base = tig >> 1;

    for (int s = 0; s < PRED; s++) {
        // ---------------- phase 1a: coalesced gather -> staging smem -------------
        {
            const int base = s * ROW2 + b0 * 40;
#pragma unroll
            for (int i = 0; i < 20; i++) {
                int idx  = tid + i * NTHR;          // 0..10239
                int gidx = base + idx;
                float v = (gidx < OBS * ROW2) ? trajAbs[gidx]
                                              : out[gidx - OBS * ROW2];
                sStage[(idx / 40) * 41 + (idx % 40)] = v;
            }
        }
        __syncthreads();

        // ---------------- phase 1b: LN1 + embed + leaky -> A cols 0..15 ----------
        {
            const int a  = tid >> 1;
            const int jt = tid & 1;
            float raw[20];
            const float* sp = sStage + a * 41 + jt * 20;
#pragma unroll
            for (int u = 0; u < 20; u++) raw[u] = sp[u];

            float sum = 0.f, sq = 0.f;
#pragma unroll
            for (int u = 0; u < 20; u++) { sum += raw[u]; sq += raw[u] * raw[u]; }
            sum += __shfl_xor_sync(0xffffffffu, sum, 1);
            sq  += __shfl_xor_sync(0xffffffffu, sq, 1);
            const float mean = sum * 0.025f;
            const float var  = sq * 0.025f - mean * mean;
            const float rstd = rsqrtf(var + 1e-5f);

            float xn[20];
#pragma unroll
            for (int u = 0; u < 20; u++) {
                int idx = jt * 20 + u;
                xn[u] = (raw[u] - mean) * rstd * sSm[O_LN1G + idx] + sSm[O_LN1B + idx];
            }
            float p[16];
#pragma unroll
            for (int e = 0; e < 16; e++) {
                const float* wrow = sSm + O_EMBW + e * 40 + jt * 20;
                float acc = 0.f;
#pragma unroll
                for (int q = 0; q < 5; q++) {
                    float4 w = *(const float4*)(wrow + 4 * q);
                    acc = fmaf(xn[4*q],   w.x, acc);
                    acc = fmaf(xn[4*q+1], w.y, acc);
                    acc = fmaf(xn[4*q+2], w.z, acc);
                    acc = fmaf(xn[4*q+3], w.w, acc);
                }
                p[e] = acc + __shfl_xor_sync(0xffffffffu, acc, 1);
            }
#pragma unroll
            for (int i = 0; i < 4; i++) {
                int e = jt * 8 + 2 * i;
                float v0 = p[e]   + sSm[O_EMBB + e];
                float v1 = p[e+1] + sSm[O_EMBB + e + 1];
                v0 = v0 > 0.f ? v0 : 0.01f * v0;
                v1 = v1 > 0.f ? v1 : 0.01f * v1;
                *(unsigned*)(sm + SM_A + a * RB + e * 2) = pkh2(v0, v1);
            }
        }
        __syncthreads();

        // ---------------- A-fragment preload via ldmatrix (m-tile = wid) ---------
        unsigned af[5][4];
#pragma unroll
        for (int kt = 0; kt < 5; kt++)
            ldsm4(af[kt][0], af[kt][1], af[kt][2], af[kt][3],
                  sb + SM_A + abase + kt * 32);
        __syncthreads();   // A tile readable done; h-writes below are for next step

        // ---------------- GEMM + fused LSTM cell + fused LN2/h2p -----------------
        float sum_h = 0.f, sq_h = 0.f, S0 = 0.f, S1 = 0.f;

        auto loadB = [&](int nt, unsigned* bq) {
            unsigned r4 = brow4_0 + nt * (8 * RB);
            ldsm4(bq[0], bq[1], bq[2], bq[3], r4);
            ldsm4(bq[4], bq[5], bq[6], bq[7], r4 + 64);
            ldsm2(bq[8], bq[9], brow2_0 + nt * (8 * RB));
        };
        auto body = [&](int nt, const unsigned* bq) {
            const int jj = 2 * nt + jj_base;
            float c_old = sC[a_loc * 66 + jj];
            float d0 = 0.f, d1 = 0.f, d2 = 0.f, d3 = 0.f;
#pragma unroll
            for (int kt = 0; kt < 5; kt++)
                mma16816(d0, d1, d2, d3, af[kt][0], af[kt][1], af[kt][2], af[kt][3],
                         bq[2*kt], bq[2*kt+1]);
            float r0 = __shfl_xor_sync(0xffffffffu, d0, 1);
            float r1 = __shfl_xor_sync(0xffffffffu, d1, 1);
            float r2 = __shfl_xor_sync(0xffffffffu, d2, 1);
            float r3 = __shfl_xor_sync(0xffffffffu, d3, 1);
            float iv = oddp ? r2 : d0;
            float fv = oddp ? r3 : d1;
            float gv = oddp ? d2 : r0;
            float ov = oddp ? d3 : r1;
            float4 bias = *(const float4*)(sBias + 4 * jj);
            iv += bias.x; fv += bias.y; gv += bias.z; ov += bias.w;

            float ig = sigmA(iv);
            float fg = sigmA(fv);
            float og = sigmA(ov);
            float gg = tanhA(gv);
            float c2 = fmaf(fg, c_old, ig * gg);
            float hv = og * tanhA(c2);
            sC[a_loc * 66 + jj] = c2;
            // write h (fp16) into A tile cols 16..79 for next step
            __half hh = __float2half(hv);
            *(__half*)(sm + SM_A + a_loc * RB + (16 + jj) * 2) = hh;

            sum_h += hv;
            sq_h   = fmaf(hv, hv, sq_h);
            float2 gw = *(const float2*)(sSm + O_GW + 2 * jj);
            S0 = fmaf(hv, gw.x, S0);
            S1 = fmaf(hv, gw.y, S1);
        };

        unsigned ba[10], bb[10];
        loadB(0, ba);
#pragma unroll 1
        for (int nt = 0; nt < 32; nt += 2) {
            loadB(nt + 1, bb);
            body(nt, ba);
            if (nt < 30) loadB(nt + 2, ba);
            body(nt + 1, bb);
        }

        // reduce across the 2 lanes sharing this agent (tig ^ 2)
        sum_h += __shfl_xor_sync(0xffffffffu, sum_h, 2);
        sq_h  += __shfl_xor_sync(0xffffffffu, sq_h, 2);
        S0    += __shfl_xor_sync(0xffffffffu, S0, 2);
        S1    += __shfl_xor_sync(0xffffffffu, S1, 2);

        if (tig < 2) {
            const float m    = sum_h * 0.015625f;
            const float var  = sq_h * 0.015625f - m * m;
            const float rstd = rsqrtf(var + 1e-5f);
            float2 r = make_float2(rstd * (S0 - m * sSm[O_SC + 0]) + sSm[O_SC + 2],
                                   rstd * (S1 - m * sSm[O_SC + 1]) + sSm[O_SC + 3]);
            *(float2*)(out + s * ROW2 + bglob * 2) = r;
        }

        // ---------------- grid barrier (skip after last step) --------------------
        if (s < PRED - 1) {
            __threadfence();
            __syncthreads();
            if (tid == 0) {
                atomicAdd(&g_bar, 1u);
                const unsigned target = (unsigned)(s + 1) * (unsigned)gridDim.x;
                while (ldvol(&g_bar) < target) __nanosleep(64);
            }
            __syncthreads();
            __threadfence();
        }
    }
}

extern "C" void kernel_launch(void* const* d_in, const int* in_sizes, int n_in,
                              void* d_out, int out_size)
{
    const float* trajAbs  = (const float*)d_in[0];
    const float* decoderH = (const float*)d_in[2];
    const float* W_ih = (const float*)d_in[3];
    const float* W_hh = (const float*)d_in[4];
    const float* b_ih = (const float*)d_in[5];
    const float* b_hh = (const float*)d_in[6];
    const float* embW = (const float*)d_in[7];
    const float* embB = (const float*)d_in[8];
    const float* h2pW = (const float*)d_in[9];
    const float* h2pB = (const float*)d_in[10];
    const float* ln1g = (const float*)d_in[11];
    const float* ln1b = (const float*)d_in[12];
    const float* ln2g = (const float*)d_in[13];
    const float* ln2b = (const float*)d_in[14];
    float* out = (float*)d_out;

    prep_kernel<<<80, 256>>>(
        W_ih, W_hh, b_ih, b_hh, embW, embB,
        ln1g, ln1b, ln2g, ln2b, h2pW, h2pB);

    cudaFuncSetAttribute(lstm_persist, cudaFuncAttributeMaxDynamicSharedMemorySize,
                         SM_TOTAL);

    lstm_persist<<<NBLK, NTHR, SM_TOTAL>>>(trajAbs, decoderH, out);
}

// round 13
// speedup vs baseline: 1.6243x; 1.0602x over previous
#include <cuda_runtime.h>
#include <cuda_fp16.h>
#include <cstring>

#define OBS   20
#define PRED  30
#define B_AG  32768
#define ROW2  65536
#define HD    64
#define ED    16
#define KD    80
#define NG    256
#define AB    256               // agents per block
#define NTHR  512
#define NBLK  (B_AG / AB)       // 128 blocks -> all co-resident (148 SMs)
#define KSTR  88                // fp16 row stride (44 words: 16B-aligned + conflict-free)
#define RB    176               // row bytes

// ---- smem byte layout ----
#define SM_W     0               // 256*176 = 45056 (fp16 W, gate-interleaved rows)
#define SM_A     45056           // 45056 (fp16 A tile: x cols 0..15, h cols 16..79)
#define SM_SMALL 90112           // 1280 floats = 5120
#define SM_C     95232           // 256*66*4 = 67584 (c state, [a][jj] stride 66)
#define SM_STAGE 162816          // 256*41*4 = 41984 (phase-1 staging; aliased as sRed)
#define SM_TOTAL 204800
// smalls float offsets
#define O_EMBW 0
#define O_EMBB 640
#define O_LN1G 656
#define O_LN1B 696
#define O_GW   736    // float2[64]: (ln2g*w0, ln2g*w1) per j
#define O_SC   864    // SGW0, SGW1, CB0, CB1
#define O_BIAS 1024   // 256 floats, gate-interleaved (n' = 4j+gate)

// prepped params (c lives in smem; no global state round-trip)
__device__ __align__(16) unsigned short g_W[NG * KSTR];
__device__ __align__(16) float          g_smalls[1280];
__device__ unsigned g_bar;     // grid barrier counter (reset by prep each replay)

// ---- helpers ----
__device__ __forceinline__ void cp16(unsigned s, const void* g) {
    asm volatile("cp.async.cg.shared.global [%0], [%1], 16;" :: "r"(s), "l"(g));
}
__device__ __forceinline__ unsigned pkh2(float a, float b) {
    __half2 t = __floats2half2_rn(a, b);
    unsigned u; memcpy(&u, &t, 4); return u;
}
__device__ __forceinline__ float tanhA(float x) {
    float r; asm("tanh.approx.f32 %0, %1;" : "=f"(r) : "f"(x)); return r;
}
__device__ __forceinline__ float sigmA(float x) {
    return fmaf(tanhA(0.5f * x), 0.5f, 0.5f);
}
__device__ __forceinline__ void ldsm4(unsigned& r0, unsigned& r1, unsigned& r2, unsigned& r3,
                                      unsigned addr) {
    asm volatile("ldmatrix.sync.aligned.m8n8.x4.shared.b16 {%0,%1,%2,%3}, [%4];"
                 : "=r"(r0), "=r"(r1), "=r"(r2), "=r"(r3) : "r"(addr));
}
__device__ __forceinline__ void ldsm2(unsigned& r0, unsigned& r1, unsigned addr) {
    asm volatile("ldmatrix.sync.aligned.m8n8.x2.shared.b16 {%0,%1}, [%2];"
                 : "=r"(r0), "=r"(r1) : "r"(addr));
}
__device__ __forceinline__ void mma16816(float& d0, float& d1, float& d2, float& d3,
                                         unsigned a0, unsigned a1, unsigned a2, unsigned a3,
                                         unsigned b0, unsigned b1) {
    asm volatile(
        "mma.sync.aligned.m16n8k16.row.col.f32.f16.f16.f32 "
        "{%0,%1,%2,%3}, {%4,%5,%6,%7}, {%8,%9}, {%0,%1,%2,%3};"
        : "+f"(d0), "+f"(d1), "+f"(d2), "+f"(d3)
        : "r"(a0), "r"(a1), "r"(a2), "r"(a3), "r"(b0), "r"(b1));
}
__device__ __forceinline__ unsigned ldvol(unsigned* p) {
    unsigned v;
    asm volatile("ld.volatile.global.u32 %0, [%1];" : "=r"(v) : "l"(p));
    return v;
}

// ---------------- one-time prep ----------------
__global__ void prep_kernel(const float* __restrict__ W_ih, const float* __restrict__ W_hh,
                            const float* __restrict__ b_ih, const float* __restrict__ b_hh,
                            const float* __restrict__ embW, const float* __restrict__ embB,
                            const float* __restrict__ ln1g, const float* __restrict__ ln1b,
                            const float* __restrict__ ln2g, const float* __restrict__ ln2b,
                            const float* __restrict__ h2pW, const float* __restrict__ h2pB)
{
    const int gid = blockIdx.x * blockDim.x + threadIdx.x;
    if (gid == 0) g_bar = 0;
    if (gid < NG * KD) {
        const int np = gid / KD;
        const int k  = gid % KD;
        const int n  = (np & 3) * HD + (np >> 2);   // gate-interleaved rows
        float w = (k < ED) ? W_ih[n * ED + k] : W_hh[n * HD + (k - ED)];
        __half h = __float2half(w);
        unsigned short hs; memcpy(&hs, &h, 2);
        g_W[np * KSTR + k] = hs;
    }
    if (gid < 1280) {
        float v;
        if (gid < 640)       v = embW[gid];
        else if (gid < 656)  v = embB[gid - 640];
        else if (gid < 696)  v = ln1g[gid - 656];
        else if (gid < 736)  v = ln1b[gid - 696];
        else if (gid < 864) {                       // gw pairs
            int q = gid - 736;
            int j = q >> 1;
            v = ln2g[j] * h2pW[(q & 1) * 64 + j];
        }
        else if (gid < 868) {                       // scalars
            int w = gid - 864;
            float acc = 0.f;
            if (w < 2) { for (int j = 0; j < 64; j++) acc += ln2g[j] * h2pW[w * 64 + j]; }
            else {
                int o = w - 2;
                for (int j = 0; j < 64; j++) acc += ln2b[j] * h2pW[o * 64 + j];
                acc += h2pB[o];
            }
            v = acc;
        }
        else if (gid >= 1024) {
            int np = gid - 1024;
            int n  = (np & 3) * HD + (np >> 2);
            v = b_ih[n] + b_hh[n];
        }
        else                 v = 0.f;
        g_smalls[gid] = v;
    }
}

// ---------------- persistent kernel: all 30 steps ----------------
__global__ void __launch_bounds__(NTHR, 1)
lstm_persist(const float* __restrict__ trajAbs,
             const float* __restrict__ decoderH,
             float* __restrict__ out)
{
    extern __shared__ char sm[];
    float* sSm    = (float*)(sm + SM_SMALL);
    float* sBias  = sSm + O_BIAS;
    float* sC     = (float*)(sm + SM_C);
    float* sStage = (float*)(sm + SM_STAGE);
    float* sRed   = sStage;                 // alias: 2*256*4 floats after phase 1

    const int tid  = threadIdx.x;
    const int lane = tid & 31;
    const int wid  = tid >> 5;
    const int b0   = blockIdx.x * AB;
    const unsigned sb = (unsigned)__cvta_generic_to_shared(sm);

    // ---- one-time: W tile (44 KB), smalls, zero c, initial h -> A cols 16..79 ----
    {
#pragma unroll
        for (int i = 0; i < 6; i++) {
            int c = tid + i * NTHR;
            if (c < 2816) cp16(sb + SM_W + c * 16, (const char*)g_W + c * 16);
        }
        asm volatile("cp.async.commit_group;");
    }
    if (tid < 320) ((float4*)sSm)[tid] = ((const float4*)g_smalls)[tid];
#pragma unroll
    for (int i = 0; i < 33; i++) sC[tid + i * NTHR] = 0.f;   // 16896 words
    {
#pragma unroll
        for (int it = 0; it < 8; it++) {
            int idx = tid + it * NTHR;       // 4096 float4s
            int a = idx >> 4;
            int j = (idx & 15) * 4;
            float4 hv = *(const float4*)(decoderH + (b0 + a) * HD + j);
            unsigned off = a * RB + (16 + j) * 2;
            *(unsigned*)(sm + SM_A + off)     = pkh2(hv.x, hv.y);
            *(unsigned*)(sm + SM_A + off + 4) = pkh2(hv.z, hv.w);
        }
    }
    asm volatile("cp.async.wait_group 0;");
    __syncthreads();

    // invariant lane/warp constants
    const int g    = lane >> 2;
    const int tig  = lane & 3;
    const int oddp = tig & 1;
    const int pr   = wid & 7;        // m-tile pair index
    const int hf   = wid >> 3;       // nt half (0: nt 0..15, 1: nt 16..31)
    const int jj_base = tig >> 1;
    int a_loc[2];
    a_loc[0] = (2 * pr) * 16 + g + (oddp ? 8 : 0);
    a_loc[1] = (2 * pr + 1) * 16 + g + (oddp ? 8 : 0);
    unsigned abase[2];
#pragma unroll
    for (int m = 0; m < 2; m++)
        abase[m] = ((2 * pr + m) * 16 + ((lane >> 3) & 1) * 8 + (lane & 7)) * RB
                 + (lane >> 4) * 16;
    const unsigned brow4_0 = sb + SM_W + (lane & 7) * RB + (lane >> 3) * 16;
    const unsigned brow2_0 = sb + SM_W + (lane & 7) * RB + 128 + ((lane >> 3) & 1) * 16;
    const int nt0 = hf * 16;

    for (int s = 0; s < PRED; s++) {
        // ---------------- phase 1a: coalesced gather -> staging smem -------------
        {
            const int base = s * ROW2 + b0 * 40;
#pragma unroll
            for (int i = 0; i < 20; i++) {
                int idx  = tid + i * NTHR;          // 0..10239
                int gidx = base + idx;
                float v = (gidx < OBS * ROW2) ? trajAbs[gidx]
                                              : out[gidx - OBS * ROW2];
                sStage[(idx / 40) * 41 + (idx % 40)] = v;
            }
        }
        __syncthreads();

        // ---------------- phase 1b: LN1 + embed + leaky -> A cols 0..15 ----------
        {
            const int a  = tid >> 1;
            const int jt = tid & 1;
            float raw[20];
            const float* sp = sStage + a * 41 + jt * 20;
#pragma unroll
            for (int u = 0; u < 20; u++) raw[u] = sp[u];

            float sum = 0.f, sq = 0.f;
#pragma unroll
            for (int u = 0; u < 20; u++) { sum += raw[u]; sq += raw[u] * raw[u]; }
            sum += __shfl_xor_sync(0xffffffffu, sum, 1);
            sq  += __shfl_xor_sync(0xffffffffu, sq, 1);
            const float mean = sum * 0.025f;
            const float var  = sq * 0.025f - mean * mean;
            const float rstd = rsqrtf(var + 1e-5f);

            float xn[20];
#pragma unroll
            for (int u = 0; u < 20; u++) {
                int idx = jt * 20 + u;
                xn[u] = (raw[u] - mean) * rstd * sSm[O_LN1G + idx] + sSm[O_LN1B + idx];
            }
            float p[16];
#pragma unroll
            for (int e = 0; e < 16; e++) {
                const float* wrow = sSm + O_EMBW + e * 40 + jt * 20;
                float acc = 0.f;
#pragma unroll
                for (int q = 0; q < 5; q++) {
                    float4 w = *(const float4*)(wrow + 4 * q);
                    acc = fmaf(xn[4*q],   w.x, acc);
                    acc = fmaf(xn[4*q+1], w.y, acc);
                    acc = fmaf(xn[4*q+2], w.z, acc);
                    acc = fmaf(xn[4*q+3], w.w, acc);
                }
                p[e] = acc + __shfl_xor_sync(0xffffffffu, acc, 1);
            }
#pragma unroll
            for (int i = 0; i < 4; i++) {
                int e = jt * 8 + 2 * i;
                float v0 = p[e]   + sSm[O_EMBB + e];
                float v1 = p[e+1] + sSm[O_EMBB + e + 1];
                v0 = v0 > 0.f ? v0 : 0.01f * v0;
                v1 = v1 > 0.f ? v1 : 0.01f * v1;
                *(unsigned*)(sm + SM_A + a * RB + e * 2) = pkh2(v0, v1);
            }
        }
        __syncthreads();

        // ---------------- A-fragment preload (2 m-tiles per warp) ----------------
        unsigned af[2][5][4];
#pragma unroll
        for (int m = 0; m < 2; m++)
#pragma unroll
            for (int kt = 0; kt < 5; kt++)
                ldsm4(af[m][kt][0], af[m][kt][1], af[m][kt][2], af[m][kt][3],
                      sb + SM_A + abase[m] + kt * 32);
        __syncthreads();   // A reads done; h-writes below are for next step

        // ---------------- GEMM + fused LSTM cell (half nt range, 2 m-tiles) ------
        float sum_h[2] = {0.f, 0.f}, sq_h[2] = {0.f, 0.f};
        float S0[2] = {0.f, 0.f}, S1[2] = {0.f, 0.f};

        auto loadB = [&](int nt, unsigned* bq) {
            unsigned r4 = brow4_0 + nt * (8 * RB);
            ldsm4(bq[0], bq[1], bq[2], bq[3], r4);
            ldsm4(bq[4], bq[5], bq[6], bq[7], r4 + 64);
            ldsm2(bq[8], bq[9], brow2_0 + nt * (8 * RB));
        };
        auto body = [&](int nt, const unsigned* bq) {
            const int jj = 2 * nt + jj_base;
            float4 bias = *(const float4*)(sBias + 4 * jj);
            float2 gw = *(const float2*)(sSm + O_GW + 2 * jj);
#pragma unroll
            for (int m = 0; m < 2; m++) {
                float c_old = sC[a_loc[m] * 66 + jj];
                float d0 = 0.f, d1 = 0.f, d2 = 0.f, d3 = 0.f;
#pragma unroll
                for (int kt = 0; kt < 5; kt++)
                    mma16816(d0, d1, d2, d3,
                             af[m][kt][0], af[m][kt][1], af[m][kt][2], af[m][kt][3],
                             bq[2*kt], bq[2*kt+1]);
                float r0 = __shfl_xor_sync(0xffffffffu, d0, 1);
                float r1 = __shfl_xor_sync(0xffffffffu, d1, 1);
                float r2 = __shfl_xor_sync(0xffffffffu, d2, 1);
                float r3 = __shfl_xor_sync(0xffffffffu, d3, 1);
                float iv = (oddp ? r2 : d0) + bias.x;
                float fv = (oddp ? r3 : d1) + bias.y;
                float gv = (oddp ? d2 : r0) + bias.z;
                float ov = (oddp ? d3 : r1) + bias.w;

                float ig = sigmA(iv);
                float fg = sigmA(fv);
                float og = sigmA(ov);
                float gg = tanhA(gv);
                float c2 = fmaf(fg, c_old, ig * gg);
                float hv = og * tanhA(c2);
                sC[a_loc[m] * 66 + jj] = c2;
                *(__half*)(sm + SM_A + a_loc[m] * RB + (16 + jj) * 2) = __float2half(hv);

                sum_h[m] += hv;
                sq_h[m]   = fmaf(hv, hv, sq_h[m]);
                S0[m] = fmaf(hv, gw.x, S0[m]);
                S1[m] = fmaf(hv, gw.y, S1[m]);
            }
        };

        unsigned ba[10], bb[10];
        loadB(nt0, ba);
#pragma unroll 1
        for (int nt = nt0; nt < nt0 + 16; nt += 2) {
            loadB(nt + 1, bb);
            body(nt, ba);
            if (nt < nt0 + 14) loadB(nt + 2, ba);
            body(nt + 1, bb);
        }

        // combine jj-parities within warp, then cross-warp via smem
#pragma unroll
        for (int m = 0; m < 2; m++) {
            sum_h[m] += __shfl_xor_sync(0xffffffffu, sum_h[m], 2);
            sq_h[m]  += __shfl_xor_sync(0xffffffffu, sq_h[m], 2);
            S0[m]    += __shfl_xor_sync(0xffffffffu, S0[m], 2);
            S1[m]    += __shfl_xor_sync(0xffffffffu, S1[m], 2);
        }
        if (tig < 2) {
#pragma unroll
            for (int m = 0; m < 2; m++) {
                int a = (2 * pr + m) * 16 + g + 8 * tig;
                *(float4*)(sRed + (hf * 256 + a) * 4) =
                    make_float4(sum_h[m], sq_h[m], S0[m], S1[m]);
            }
        }
        __syncthreads();

        if (tid < 256) {
            float4 u = *(const float4*)(sRed + tid * 4);
            float4 v = *(const float4*)(sRed + (256 + tid) * 4);
            const float sum = u.x + v.x, sq = u.y + v.y;
            const float s0 = u.z + v.z, s1 = u.w + v.w;
            const float m    = sum * 0.015625f;
            const float var  = sq * 0.015625f - m * m;
            const float rstd = rsqrtf(var + 1e-5f);
            float2 r = make_float2(rstd * (s0 - m * sSm[O_SC + 0]) + sSm[O_SC + 2],
                                   rstd * (s1 - m * sSm[O_SC + 1]) + sSm[O_SC + 3]);
            *(float2*)(out + s * ROW2 + (b0 + tid) * 2) = r;
        }

        // ---------------- grid barrier (skip after last step) --------------------
        if (s < PRED - 1) {
            __threadfence();
            __syncthreads();
            if (tid == 0) {
                atomicAdd(&g_bar, 1u);
                const unsigned target = (unsigned)(s + 1) * (unsigned)gridDim.x;
                while (ldvol(&g_bar) < target) __nanosleep(64);
            }
            __syncthreads();
            __threadfence();
        }
    }
}

extern "C" void kernel_launch(void* const* d_in, const int* in_sizes, int n_in,
                              void* d_out, int out_size)
{
    const float* trajAbs  = (const float*)d_in[0];
    const float* decoderH = (const float*)d_in[2];
    const float* W_ih = (const float*)d_in[3];
    const float* W_hh = (const float*)d_in[4];
    const float* b_ih = (const float*)d_in[5];
    const float* b_hh = (const float*)d_in[6];
    const float* embW = (const float*)d_in[7];
    const float* embB = (const float*)d_in[8];
    const float* h2pW = (const float*)d_in[9];
    const float* h2pB = (const float*)d_in[10];
    const float* ln1g = (const float*)d_in[11];
    const float* ln1b = (const float*)d_in[12];
    const float* ln2g = (const float*)d_in[13];
    const float* ln2b = (const float*)d_in[14];
    float* out = (float*)d_out;

    prep_kernel<<<80, 256>>>(
        W_ih, W_hh, b_ih, b_hh, embW, embB,
        ln1g, ln1b, ln2g, ln2b, h2pW, h2pB);

    cudaFuncSetAttribute(lstm_persist, cudaFuncAttributeMaxDynamicSharedMemorySize,
                         SM_TOTAL);

    lstm_persist<<<NBLK, NTHR, SM_TOTAL>>>(trajAbs, decoderH, out);
}